// round 14
// baseline (speedup 1.0000x reference)
#include <cuda_runtime.h>
#include <cuda_bf16.h>
#include <cuda_fp16.h>
#include <math_constants.h>
#include <cstdint>
#include <cstddef>

#define BATCH 4
#define NH    16
#define SEQ   2048
#define DH    128
#define DM    2048
#define BH    (BATCH*NH)     // 64
#define MROWS (BATCH*SEQ)    // 8192

typedef __nv_bfloat16 bf16;
typedef __half fp16;

// ---------------------------------------------------------------------------
// Device scratch (static globals; keep total < 2 GB for x86 link)
// ---------------------------------------------------------------------------
__device__ bf16 g_Hh[(size_t)MROWS * DM];
__device__ bf16 g_Hm[(size_t)MROWS * DM];
__device__ bf16 g_Wh3[3][(size_t)DM * DM];   // wq, wk, wv (hi)
__device__ bf16 g_Wm3[3][(size_t)DM * DM];   // wq, wk, wv (mid)
__device__ fp16 g_Wo16[(size_t)DM * DM];     // wo single fp16
__device__ bf16 g_Qh[(size_t)BH * SEQ * DH];
__device__ bf16 g_Qm[(size_t)BH * SEQ * DH];
__device__ bf16 g_Kh[(size_t)BH * SEQ * DH];
__device__ bf16 g_Km[(size_t)BH * SEQ * DH];
__device__ fp16 g_V16[(size_t)BH * SEQ * DH];    // V single fp16 [bh,s,dh]
__device__ fp16 g_Vt16[(size_t)BH * DH * SEQ];   // V^T single fp16 [bh,dh,s]
// g_S: 1 GiB. fp32 scores; softmax overwrites each 8KB row IN PLACE with
// SINGLE fp16 probs at fp16 offsets [0,2048) (row stride 4096 fp16).
__device__ float g_S[(size_t)BH * SEQ * SEQ];
__device__ fp16 g_AO16[(size_t)MROWS * DM];  // attn-out single fp16

// ---------------------------------------------------------------------------
// PTX helpers (sm_80-era: mma.sync / ldmatrix / cp.async — valid on sm_100)
// ---------------------------------------------------------------------------
__device__ __forceinline__ uint32_t smem_u32(const void* p) {
    uint32_t a;
    asm("{ .reg .u64 t; cvta.to.shared.u64 t, %1; cvt.u32.u64 %0, t; }"
        : "=r"(a) : "l"(p));
    return a;
}

#define LDSM_X4(R, addr) \
    asm volatile("ldmatrix.sync.aligned.m8n8.x4.shared.b16 {%0,%1,%2,%3}, [%4];" \
                 : "=r"((R)[0]), "=r"((R)[1]), "=r"((R)[2]), "=r"((R)[3]) : "r"(addr))

__device__ __forceinline__ void mma_bf16(float* c, const uint32_t* a,
                                         uint32_t b0, uint32_t b1) {
    asm volatile(
        "mma.sync.aligned.m16n8k16.row.col.f32.bf16.bf16.f32 "
        "{%0,%1,%2,%3}, {%4,%5,%6,%7}, {%8,%9}, {%0,%1,%2,%3};"
        : "+f"(c[0]), "+f"(c[1]), "+f"(c[2]), "+f"(c[3])
        : "r"(a[0]), "r"(a[1]), "r"(a[2]), "r"(a[3]), "r"(b0), "r"(b1));
}

__device__ __forceinline__ void mma_f16(float* c, const uint32_t* a,
                                        uint32_t b0, uint32_t b1) {
    asm volatile(
        "mma.sync.aligned.m16n8k16.row.col.f32.f16.f16.f32 "
        "{%0,%1,%2,%3}, {%4,%5,%6,%7}, {%8,%9}, {%0,%1,%2,%3};"
        : "+f"(c[0]), "+f"(c[1]), "+f"(c[2]), "+f"(c[3])
        : "r"(a[0]), "r"(a[1]), "r"(a[2]), "r"(a[3]), "r"(b0), "r"(b1));
}

__device__ __forceinline__ void cp16(uint32_t s, const void* g) {
    asm volatile("cp.async.cg.shared.global [%0], [%1], 16;" :: "r"(s), "l"(g));
}
#define CP_COMMIT() asm volatile("cp.async.commit_group;" ::: "memory")
#define CP_WAIT1()  asm volatile("cp.async.wait_group 1;"  ::: "memory")
#define CP_WAIT0()  asm volatile("cp.async.wait_group 0;"  ::: "memory")

__device__ __forceinline__ void split_bf16(float v, bf16& h, bf16& m) {
    h = __float2bfloat16(v);
    m = __float2bfloat16(v - __bfloat162float(h));
}

// 64B-row swizzle: 16B chunk index XORed with row bits [2:1] -> conflict-free LDSM
__device__ __forceinline__ uint32_t swz64(int r, int ch) {
    return (uint32_t)(r * 64 + (((unsigned)ch ^ (((unsigned)r >> 1) & 3u)) << 4));
}

// ---------------------------------------------------------------------------
// 3-split bf16 mainloop: stage 32KB (Ah 8K, Am 8K, Bh 8K, Bm 8K), 3 stages.
// MMA issue order is term-outer / accumulator-interleaved so each fp32
// accumulator's dependent HMMAs sit 4 instructions apart (was 2).
// Accumulation order per accumulator is unchanged (HH, HM, MH) -> bit-identical.
// ---------------------------------------------------------------------------
#define STAGE_B    32768
#define OFF_AM     8192
#define OFF_BH     16384
#define OFF_BM     24576
#define SMEM_GEMM  (3 * STAGE_B)    // 98304

__device__ __forceinline__ void gemm_mainloop(
    uint32_t sb,
    const bf16* __restrict__ Ah, const bf16* __restrict__ Am, int lda,
    const bf16* __restrict__ Bh, const bf16* __restrict__ Bm, int ldb,
    int chunks, float (&acc)[2][8][4])
{
#pragma unroll
    for (int a = 0; a < 2; a++)
#pragma unroll
        for (int b = 0; b < 8; b++)
#pragma unroll
            for (int cc = 0; cc < 4; cc++) acc[a][b][cc] = 0.f;

    const int tid = threadIdx.x, lane = tid & 31, wid = tid >> 5;
    const int wm = wid >> 1, wn = wid & 1;

    const int rA = wm * 32 + (lane & 15);
    const int hA = lane >> 4;
    const int rB = wn * 64 + (lane & 7) + ((lane >> 4) & 1) * 8;
    const int hB = (lane >> 3) & 1;

    const int r  = tid >> 1;
    const int c0 = (tid & 1) * 2;
    const uint32_t so0 = swz64(r, c0);
    const uint32_t so1 = swz64(r, c0 + 1);
    const bf16* pAh = Ah + (size_t)r * lda + c0 * 8;
    const bf16* pAm = Am + (size_t)r * lda + c0 * 8;
    const bf16* pBh = Bh + (size_t)r * ldb + c0 * 8;
    const bf16* pBm = Bm + (size_t)r * ldb + c0 * 8;

#define ISSUE_STAGE3(SBUF) do {                         \
        const uint32_t _b = (SBUF);                     \
        cp16(_b + so0,          pAh);                   \
        cp16(_b + so1,          pAh + 8);               \
        cp16(_b + OFF_AM + so0, pAm);                   \
        cp16(_b + OFF_AM + so1, pAm + 8);               \
        cp16(_b + OFF_BH + so0, pBh);                   \
        cp16(_b + OFF_BH + so1, pBh + 8);               \
        cp16(_b + OFF_BM + so0, pBm);                   \
        cp16(_b + OFF_BM + so1, pBm + 8);               \
        pAh += 32; pAm += 32; pBh += 32; pBm += 32;     \
        CP_COMMIT();                                    \
    } while (0)

    ISSUE_STAGE3(sb);
    ISSUE_STAGE3(sb + STAGE_B);

    int stage = 0, pstage = 2;
    for (int c = 0; c < chunks; c++) {
        if (c + 1 < chunks) CP_WAIT1(); else CP_WAIT0();
        __syncthreads();
        if (c + 2 < chunks) ISSUE_STAGE3(sb + pstage * STAGE_B);
        const uint32_t buf = sb + stage * STAGE_B;
#pragma unroll
        for (int k16 = 0; k16 < 2; k16++) {
            uint32_t aH[2][4], aM[2][4];
#pragma unroll
            for (int mb = 0; mb < 2; mb++) {
                const uint32_t off = swz64(rA + mb * 16, k16 * 2 + hA);
                LDSM_X4(aH[mb], buf + off);
                LDSM_X4(aM[mb], buf + OFF_AM + off);
            }
#pragma unroll
            for (int nb = 0; nb < 4; nb++) {
                const uint32_t offB = swz64(rB + nb * 16, k16 * 2 + hB);
                uint32_t bH[4], bM[4];
                LDSM_X4(bH, buf + OFF_BH + offB);
                LDSM_X4(bM, buf + OFF_BM + offB);
                // term HH: 4 independent accumulators back-to-back
                mma_bf16(acc[0][nb * 2 + 0], aH[0], bH[0], bH[1]);
                mma_bf16(acc[1][nb * 2 + 0], aH[1], bH[0], bH[1]);
                mma_bf16(acc[0][nb * 2 + 1], aH[0], bH[2], bH[3]);
                mma_bf16(acc[1][nb * 2 + 1], aH[1], bH[2], bH[3]);
                // term HM
                mma_bf16(acc[0][nb * 2 + 0], aH[0], bM[0], bM[1]);
                mma_bf16(acc[1][nb * 2 + 0], aH[1], bM[0], bM[1]);
                mma_bf16(acc[0][nb * 2 + 1], aH[0], bM[2], bM[3]);
                mma_bf16(acc[1][nb * 2 + 1], aH[1], bM[2], bM[3]);
                // term MH
                mma_bf16(acc[0][nb * 2 + 0], aM[0], bH[0], bH[1]);
                mma_bf16(acc[1][nb * 2 + 0], aM[1], bH[0], bH[1]);
                mma_bf16(acc[0][nb * 2 + 1], aM[0], bH[2], bH[3]);
                mma_bf16(acc[1][nb * 2 + 1], aM[1], bH[2], bH[3]);
            }
        }
        stage = (stage == 2) ? 0 : stage + 1;
        pstage = (pstage == 2) ? 0 : pstage + 1;
    }
    __syncthreads();
#undef ISSUE_STAGE3
}

// ---------------------------------------------------------------------------
// fp16 1x1 mainloop: A single fp16, B single fp16. Stage 16KB, 3 stages.
// ---------------------------------------------------------------------------
#define STAGE11_B   16384
#define OFF11_B     8192
#define SMEM_GEMM11 (3 * STAGE11_B)   // 49152

__device__ __forceinline__ void gemm_mainloop_11(
    uint32_t sb,
    const fp16* __restrict__ A, int lda,
    const fp16* __restrict__ B, int ldb,
    int chunks, float (&acc)[2][8][4])
{
#pragma unroll
    for (int a = 0; a < 2; a++)
#pragma unroll
        for (int b = 0; b < 8; b++)
#pragma unroll
            for (int cc = 0; cc < 4; cc++) acc[a][b][cc] = 0.f;

    const int tid = threadIdx.x, lane = tid & 31, wid = tid >> 5;
    const int wm = wid >> 1, wn = wid & 1;

    const int rA = wm * 32 + (lane & 15);
    const int hA = lane >> 4;
    const int rB = wn * 64 + (lane & 7) + ((lane >> 4) & 1) * 8;
    const int hB = (lane >> 3) & 1;

    const int r  = tid >> 1;
    const int c0 = (tid & 1) * 2;
    const uint32_t so0 = swz64(r, c0);
    const uint32_t so1 = swz64(r, c0 + 1);
    const fp16* pA = A + (size_t)r * lda + c0 * 8;
    const fp16* pB = B + (size_t)r * ldb + c0 * 8;

#define ISSUE_STAGE11(SBUF) do {                        \
        const uint32_t _b = (SBUF);                     \
        cp16(_b + so0,           pA);                   \
        cp16(_b + so1,           pA + 8);               \
        cp16(_b + OFF11_B + so0, pB);                   \
        cp16(_b + OFF11_B + so1, pB + 8);               \
        pA += 32; pB += 32;                             \
        CP_COMMIT();                                    \
    } while (0)

    ISSUE_STAGE11(sb);
    ISSUE_STAGE11(sb + STAGE11_B);

    int stage = 0, pstage = 2;
    for (int c = 0; c < chunks; c++) {
        if (c + 1 < chunks) CP_WAIT1(); else CP_WAIT0();
        __syncthreads();
        if (c + 2 < chunks) ISSUE_STAGE11(sb + pstage * STAGE11_B);
        const uint32_t buf = sb + stage * STAGE11_B;
#pragma unroll
        for (int k16 = 0; k16 < 2; k16++) {
            uint32_t aV[2][4];
#pragma unroll
            for (int mb = 0; mb < 2; mb++) {
                const uint32_t off = swz64(rA + mb * 16, k16 * 2 + hA);
                LDSM_X4(aV[mb], buf + off);
            }
#pragma unroll
            for (int nb = 0; nb < 4; nb++) {
                const uint32_t offB = swz64(rB + nb * 16, k16 * 2 + hB);
                uint32_t bV[4];
                LDSM_X4(bV, buf + OFF11_B + offB);
#pragma unroll
                for (int mb = 0; mb < 2; mb++) {
                    mma_f16(acc[mb][nb * 2 + 0], aV[mb], bV[0], bV[1]);
                    mma_f16(acc[mb][nb * 2 + 1], aV[mb], bV[2], bV[3]);
                }
            }
        }
        stage = (stage == 2) ? 0 : stage + 1;
        pstage = (pstage == 2) ? 0 : pstage + 1;
    }
    __syncthreads();
#undef ISSUE_STAGE11
}

// Epilogue coordinates: acc[mb][j][reg]
//   row_local = wm*32 + mb*16 + (lane>>2) + (reg>=2)*8
//   col_local = wn*64 + j*8 + (lane&3)*2 + (reg&1)

// ---------------------------------------------------------------------------
// Kernel: ALL input conversions in one launch (flat quad index).
// ---------------------------------------------------------------------------
__global__ void __launch_bounds__(256)
k_convert_all(const float* __restrict__ hs, const float* __restrict__ wq,
              const float* __restrict__ wk, const float* __restrict__ wv,
              const float* __restrict__ wo) {
    const long NH4 = (long)MROWS * DM / 4;   // 4,194,304
    const long NW4 = (long)DM * DM / 4;      // 1,048,576
    long i = (long)blockIdx.x * blockDim.x + threadIdx.x;

    const float* src;
    long off;
    int sel;
    if (i < NH4) { src = hs; off = i; sel = 0; }
    else {
        long j = i - NH4;
        int w = (int)(j >> 20);               // NW4 == 2^20
        off = j & (NW4 - 1);
        sel = w + 1;
        src = (w == 0) ? wq : (w == 1) ? wk : (w == 2) ? wv : wo;
    }
    float4 v = ((const float4*)src)[off];
    if (sel == 4) {
        alignas(8) fp16 h[4];
        h[0] = __float2half(v.x); h[1] = __float2half(v.y);
        h[2] = __float2half(v.z); h[3] = __float2half(v.w);
        *(uint2*)(g_Wo16 + off * 4) = *(const uint2*)h;
        return;
    }
    bf16 *H, *M;
    if (sel == 0) { H = g_Hh; M = g_Hm; }
    else          { H = g_Wh3[sel - 1]; M = g_Wm3[sel - 1]; }
    alignas(8) bf16 h[4], m[4];
    split_bf16(v.x, h[0], m[0]);
    split_bf16(v.y, h[1], m[1]);
    split_bf16(v.z, h[2], m[2]);
    split_bf16(v.w, h[3], m[3]);
    *(uint2*)(H + off * 4) = *(const uint2*)h;
    *(uint2*)(M + off * 4) = *(const uint2*)m;
}

// ---------------------------------------------------------------------------
// Kernel: Q/K/V projection (bf16 3-split GEMM; Q,K -> bf16 splits, V ->
// single fp16). grid (nt, mt, which=3).
// ---------------------------------------------------------------------------
__global__ void __launch_bounds__(256, 2)
k_proj(void) {
    extern __shared__ char sm[];
    const uint32_t sb = smem_u32(sm);
    const int nt = blockIdx.x, mt = blockIdx.y, which = blockIdx.z;

    float acc[2][8][4];
    gemm_mainloop(sb,
        g_Hh + (size_t)mt * 128 * DM, g_Hm + (size_t)mt * 128 * DM, DM,
        g_Wh3[which] + (size_t)nt * 128 * DM, g_Wm3[which] + (size_t)nt * 128 * DM, DM,
        DM / 32, acc);

    const int tid = threadIdx.x, lane = tid & 31, wid = tid >> 5;
    const int wm = wid >> 1, wn = wid & 1;

    if (which == 2) {  // V -> single fp16
#pragma unroll
        for (int mb = 0; mb < 2; mb++)
#pragma unroll
            for (int rp = 0; rp < 2; rp++) {
                const int m = mt * 128 + wm * 32 + mb * 16 + (lane >> 2) + rp * 8;
                const int b = m >> 11, s = m & (SEQ - 1);
                fp16* pv = g_V16 + ((size_t)(b * NH + nt) * SEQ + s) * DH;
#pragma unroll
                for (int j = 0; j < 8; j++) {
                    const int col = wn * 64 + j * 8 + (lane & 3) * 2;
                    __half2 hv = __floats2half2_rn(acc[mb][j][rp * 2 + 0],
                                                   acc[mb][j][rp * 2 + 1]);
                    *(__half2*)(pv + col) = hv;
                }
            }
        return;
    }

    bf16* Gh = (which == 0) ? g_Qh : g_Kh;
    bf16* Gm = (which == 0) ? g_Qm : g_Km;
#pragma unroll
    for (int mb = 0; mb < 2; mb++)
#pragma unroll
        for (int rp = 0; rp < 2; rp++) {
            const int m = mt * 128 + wm * 32 + mb * 16 + (lane >> 2) + rp * 8;
            const int b = m >> 11, s = m & (SEQ - 1);
            bf16* ph = Gh + ((size_t)(b * NH + nt) * SEQ + s) * DH;
            bf16* pm = Gm + ((size_t)(b * NH + nt) * SEQ + s) * DH;
#pragma unroll
            for (int j = 0; j < 8; j++) {
                const int col = wn * 64 + j * 8 + (lane & 3) * 2;
                bf16 h0, m0, h1, m1;
                split_bf16(acc[mb][j][rp * 2 + 0], h0, m0);
                split_bf16(acc[mb][j][rp * 2 + 1], h1, m1);
                *(__nv_bfloat162*)(ph + col) = __nv_bfloat162(h0, h1);
                *(__nv_bfloat162*)(pm + col) = __nv_bfloat162(m0, m1);
            }
        }
}

// ---------------------------------------------------------------------------
// Kernel: transpose V [bh,s,dh] -> [bh,dh,s] (single fp16)
// ---------------------------------------------------------------------------
__global__ void __launch_bounds__(256)
k_transpose() {
    __shared__ fp16 tile[32][33];
    const int d0 = blockIdx.x * 32;
    const int s0 = blockIdx.y * 32;
    const int bh = blockIdx.z;
    const int tx = threadIdx.x, ty = threadIdx.y;
#pragma unroll
    for (int r = 0; r < 4; r++)
        tile[ty + r * 8][tx] =
            g_V16[(size_t)bh * SEQ * DH + (size_t)(s0 + ty + r * 8) * DH + d0 + tx];
    __syncthreads();
#pragma unroll
    for (int r = 0; r < 4; r++)
        g_Vt16[(size_t)bh * DH * SEQ + (size_t)(d0 + ty + r * 8) * SEQ + s0 + tx] =
            tile[tx][ty + r * 8];
}

// ---------------------------------------------------------------------------
// Kernel: causal scores = Q . K^T (fp32 to g_S). Triangular launch.
// ---------------------------------------------------------------------------
__global__ void __launch_bounds__(256, 2)
k_scores() {
    const int t = blockIdx.x;
    int bi = (int)((sqrtf(8.f * (float)t + 1.f) - 1.f) * 0.5f);
    if ((bi + 1) * (bi + 2) / 2 <= t) bi++;
    else if (bi * (bi + 1) / 2 > t) bi--;
    const int bj = t - bi * (bi + 1) / 2;
    const int bh = blockIdx.y;

    extern __shared__ char sm[];
    const uint32_t sb = smem_u32(sm);

    const size_t hb = (size_t)bh * SEQ * DH;
    float acc[2][8][4];
    gemm_mainloop(sb,
        g_Qh + hb + (size_t)bi * 128 * DH, g_Qm + hb + (size_t)bi * 128 * DH, DH,
        g_Kh + hb + (size_t)bj * 128 * DH, g_Km + hb + (size_t)bj * 128 * DH, DH,
        DH / 32, acc);

    const int tid = threadIdx.x, lane = tid & 31, wid = tid >> 5;
    const int wm = wid >> 1, wn = wid & 1;
    float* Sp = g_S + (size_t)bh * SEQ * SEQ;
#pragma unroll
    for (int mb = 0; mb < 2; mb++)
#pragma unroll
        for (int rp = 0; rp < 2; rp++) {
            const int m = bi * 128 + wm * 32 + mb * 16 + (lane >> 2) + rp * 8;
            float* dst = Sp + (size_t)m * SEQ + bj * 128;
#pragma unroll
            for (int j = 0; j < 8; j++) {
                const int col = wn * 64 + j * 8 + (lane & 3) * 2;
                *(float2*)(dst + col) =
                    make_float2(acc[mb][j][rp * 2], acc[mb][j][rp * 2 + 1]);
            }
        }
}

// ---------------------------------------------------------------------------
// Kernel: row softmax (vectorized, causal-skipped loads). In-place single
// fp16 probs into the g_S row; fp32 probs to Pext when use_ext.
// ---------------------------------------------------------------------------
__device__ __forceinline__ float warp_max(float v) {
#pragma unroll
    for (int o = 16; o > 0; o >>= 1) v = fmaxf(v, __shfl_xor_sync(0xffffffffu, v, o));
    return v;
}
__device__ __forceinline__ float warp_sum(float v) {
#pragma unroll
    for (int o = 16; o > 0; o >>= 1) v += __shfl_xor_sync(0xffffffffu, v, o);
    return v;
}

__global__ void __launch_bounds__(256)
k_softmax(float* __restrict__ Pext, int use_ext) {
    __shared__ float shm[8];
    __shared__ float shs[8];

    const size_t row = blockIdx.x;
    const int q = (int)(row & (SEQ - 1));
    const float* pr = g_S + row * (size_t)SEQ;
    const int tid = threadIdx.x;
    const int wid = tid >> 5, lid = tid & 31;
    const int jb = tid * 8;

    float v[8];
    if (jb <= q) {
        float4 a = *(const float4*)(pr + jb);
        float4 b = *(const float4*)(pr + jb + 4);
        v[0] = a.x; v[1] = a.y; v[2] = a.z; v[3] = a.w;
        v[4] = b.x; v[5] = b.y; v[6] = b.z; v[7] = b.w;
#pragma unroll
        for (int k = 0; k < 8; k++)
            if (jb + k > q) v[k] = -CUDART_INF_F;
    } else {
#pragma unroll
        for (int k = 0; k < 8; k++) v[k] = -CUDART_INF_F;
    }
    float m = -CUDART_INF_F;
#pragma unroll
    for (int k = 0; k < 8; k++) m = fmaxf(m, v[k]);
    m = warp_max(m);
    if (lid == 0) shm[wid] = m;
    __syncthreads();          // all row reads precede in-place writes
    if (tid < 32) {
        float t = (tid < 8) ? shm[tid] : -CUDART_INF_F;
        t = warp_max(t);
        if (tid == 0) shm[0] = t;
    }
    __syncthreads();
    m = shm[0];

    float s = 0.f;
#pragma unroll
    for (int k = 0; k < 8; k++) {
        const float e = expf(v[k] - m);
        v[k] = e;
        s += e;
    }
    s = warp_sum(s);
    if (lid == 0) shs[wid] = s;
    __syncthreads();
    if (tid < 32) {
        float t = (tid < 8) ? shs[tid] : 0.f;
        t = warp_sum(t);
        if (tid == 0) shs[0] = t;
    }
    __syncthreads();
    const float inv = 1.f / shs[0];

#pragma unroll
    for (int k = 0; k < 8; k++) v[k] *= inv;

    if (use_ext) {
        float* po = Pext + row * (size_t)SEQ + jb;
        *(float4*)(po)     = make_float4(v[0], v[1], v[2], v[3]);
        *(float4*)(po + 4) = make_float4(v[4], v[5], v[6], v[7]);
    }

    const int jmax = ((q >> 7) + 1) << 7;      // 128-aligned
    if (jb < jmax) {
        fp16* ph = (fp16*)(g_S) + row * (size_t)(2 * SEQ) + jb;  // row = 8KB
        alignas(16) fp16 h[8];
#pragma unroll
        for (int k = 0; k < 8; k++) h[k] = __float2half(v[k]);
        *(uint4*)ph = *(const uint4*)h;
    }
}

// ---------------------------------------------------------------------------
// Kernel: AV = P . V (fp16 single x single, causal-truncated).
// grid (bh=64, ybi=16), longest-first. Epilogue: single fp16 into g_AO16.
// ---------------------------------------------------------------------------
__global__ void __launch_bounds__(256, 2)
k_av() {
    const int bh = blockIdx.x;
    const int bi = 15 - (int)blockIdx.y;
    extern __shared__ char sm[];
    const uint32_t sb = smem_u32(sm);

    const fp16* Pbase = (const fp16*)(g_S) +
                        (size_t)(bh * SEQ + bi * 128) * (size_t)(2 * SEQ);

    float acc[2][8][4];
    gemm_mainloop_11(sb,
        Pbase, 2 * SEQ,
        g_Vt16 + (size_t)bh * DH * SEQ, SEQ,
        (bi + 1) * 4, acc);

    const int tid = threadIdx.x, lane = tid & 31, wid = tid >> 5;
    const int wm = wid >> 1, wn = wid & 1;
    const int b = bh >> 4, h = bh & 15;
#pragma unroll
    for (int mb = 0; mb < 2; mb++)
#pragma unroll
        for (int rp = 0; rp < 2; rp++) {
            const int s = bi * 128 + wm * 32 + mb * 16 + (lane >> 2) + rp * 8;
            fp16* po = g_AO16 + ((size_t)(b * SEQ + s)) * DM + h * 128;
#pragma unroll
            for (int j = 0; j < 8; j++) {
                const int col = wn * 64 + j * 8 + (lane & 3) * 2;
                __half2 hv = __floats2half2_rn(acc[mb][j][rp * 2 + 0],
                                               acc[mb][j][rp * 2 + 1]);
                *(__half2*)(po + col) = hv;
            }
        }
}

// ---------------------------------------------------------------------------
// Kernel: out = AO . Wo^T + bo (fp16 single x single, fp32 to d_out).
// ---------------------------------------------------------------------------
__global__ void __launch_bounds__(256, 2)
k_out(const float* __restrict__ bias, float* __restrict__ Out) {
    extern __shared__ char sm[];
    const uint32_t sb = smem_u32(sm);
    const int nt = blockIdx.x, mt = blockIdx.y;

    float acc[2][8][4];
    gemm_mainloop_11(sb,
        g_AO16 + (size_t)mt * 128 * DM, DM,
        g_Wo16 + (size_t)nt * 128 * DM, DM,
        DM / 32, acc);

    const int tid = threadIdx.x, lane = tid & 31, wid = tid >> 5;
    const int wm = wid >> 1, wn = wid & 1;
#pragma unroll
    for (int mb = 0; mb < 2; mb++)
#pragma unroll
        for (int rp = 0; rp < 2; rp++) {
            const int m = mt * 128 + wm * 32 + mb * 16 + (lane >> 2) + rp * 8;
            float* dst = Out + (size_t)m * DM + nt * 128;
#pragma unroll
            for (int j = 0; j < 8; j++) {
                const int col = wn * 64 + j * 8 + (lane & 3) * 2;
                *(float2*)(dst + col) =
                    make_float2(acc[mb][j][rp * 2] + bias[nt * 128 + col],
                                acc[mb][j][rp * 2 + 1] + bias[nt * 128 + col + 1]);
            }
        }
}

// ---------------------------------------------------------------------------
// Launch
// ---------------------------------------------------------------------------
extern "C" void kernel_launch(void* const* d_in, const int* in_sizes, int n_in,
                              void* d_out, int out_size) {
    const float* hs = (const float*)d_in[0];
    const float* wq = (const float*)d_in[1];
    const float* wk = (const float*)d_in[2];
    const float* wv = (const float*)d_in[3];
    const float* wo = (const float*)d_in[4];
    const float* bo = (const float*)d_in[5];
    float* out = (float*)d_out;

    const long long OUT_ELEMS = (long long)MROWS * DM;       // 16,777,216
    const long long WEI_ELEMS = (long long)BH * SEQ * SEQ;   // 268,435,456
    const int use_ext = ((long long)out_size >= OUT_ELEMS + WEI_ELEMS) ? 1 : 0;
    float* Pext = use_ext ? (out + OUT_ELEMS) : nullptr;

    cudaFuncSetAttribute(k_proj,   cudaFuncAttributeMaxDynamicSharedMemorySize, SMEM_GEMM);
    cudaFuncSetAttribute(k_scores, cudaFuncAttributeMaxDynamicSharedMemorySize, SMEM_GEMM);
    cudaFuncSetAttribute(k_av,     cudaFuncAttributeMaxDynamicSharedMemorySize, SMEM_GEMM11);
    cudaFuncSetAttribute(k_out,    cudaFuncAttributeMaxDynamicSharedMemorySize, SMEM_GEMM11);

    const long NH4 = (long)MROWS * DM / 4;   // 4,194,304
    const long NW4 = (long)DM * DM / 4;      // 1,048,576
    const long totq = NH4 + 4 * NW4;         // 8,388,608
    k_convert_all<<<(unsigned)((totq + 255) / 256), 256>>>(hs, wq, wk, wv, wo);

    k_proj<<<dim3(16, 64, 3), 256, SMEM_GEMM>>>();

    k_transpose<<<dim3(4, 64, BH), dim3(32, 8)>>>();

    k_scores<<<dim3(136, BH), 256, SMEM_GEMM>>>();
    k_softmax<<<BH * SEQ, 256>>>(Pext, use_ext);
    k_av<<<dim3(BH, 16), 256, SMEM_GEMM11>>>();
    k_out<<<dim3(16, 64), 256, SMEM_GEMM11>>>(bo, out);
}

// round 15
// speedup vs baseline: 1.0067x; 1.0067x over previous
#include <cuda_runtime.h>
#include <cuda_bf16.h>
#include <cuda_fp16.h>
#include <math_constants.h>
#include <cstdint>
#include <cstddef>

#define BATCH 4
#define NH    16
#define SEQ   2048
#define DH    128
#define DM    2048
#define BH    (BATCH*NH)     // 64
#define MROWS (BATCH*SEQ)    // 8192

typedef __nv_bfloat16 bf16;
typedef __half fp16;

// ---------------------------------------------------------------------------
// Device scratch (static globals; keep total < 2 GB for x86 link)
// ---------------------------------------------------------------------------
__device__ bf16 g_Hh[(size_t)MROWS * DM];
__device__ bf16 g_Hm[(size_t)MROWS * DM];
__device__ bf16 g_Wh3[3][(size_t)DM * DM];   // wq, wk, wv (hi)
__device__ bf16 g_Wm3[3][(size_t)DM * DM];   // wq, wk, wv (mid)
__device__ fp16 g_Wo16[(size_t)DM * DM];     // wo single fp16
__device__ bf16 g_Qh[(size_t)BH * SEQ * DH];
__device__ bf16 g_Qm[(size_t)BH * SEQ * DH];
__device__ bf16 g_Kh[(size_t)BH * SEQ * DH];
__device__ bf16 g_Km[(size_t)BH * SEQ * DH];
__device__ fp16 g_V16[(size_t)BH * SEQ * DH];    // V single fp16 [bh,s,dh]
__device__ fp16 g_Vt16[(size_t)BH * DH * SEQ];   // V^T single fp16 [bh,dh,s]
// g_S: 1 GiB. fp32 scores; softmax overwrites each 8KB row IN PLACE with
// SINGLE fp16 probs at fp16 offsets [0,2048) (row stride 4096 fp16).
__device__ float g_S[(size_t)BH * SEQ * SEQ];
__device__ fp16 g_AO16[(size_t)MROWS * DM];  // attn-out single fp16

// ---------------------------------------------------------------------------
// PTX helpers (sm_80-era: mma.sync / ldmatrix / cp.async — valid on sm_100)
// ---------------------------------------------------------------------------
__device__ __forceinline__ uint32_t smem_u32(const void* p) {
    uint32_t a;
    asm("{ .reg .u64 t; cvta.to.shared.u64 t, %1; cvt.u32.u64 %0, t; }"
        : "=r"(a) : "l"(p));
    return a;
}

#define LDSM_X4(R, addr) \
    asm volatile("ldmatrix.sync.aligned.m8n8.x4.shared.b16 {%0,%1,%2,%3}, [%4];" \
                 : "=r"((R)[0]), "=r"((R)[1]), "=r"((R)[2]), "=r"((R)[3]) : "r"(addr))

__device__ __forceinline__ void mma_bf16(float* c, const uint32_t* a,
                                         uint32_t b0, uint32_t b1) {
    asm volatile(
        "mma.sync.aligned.m16n8k16.row.col.f32.bf16.bf16.f32 "
        "{%0,%1,%2,%3}, {%4,%5,%6,%7}, {%8,%9}, {%0,%1,%2,%3};"
        : "+f"(c[0]), "+f"(c[1]), "+f"(c[2]), "+f"(c[3])
        : "r"(a[0]), "r"(a[1]), "r"(a[2]), "r"(a[3]), "r"(b0), "r"(b1));
}

__device__ __forceinline__ void mma_f16(float* c, const uint32_t* a,
                                        uint32_t b0, uint32_t b1) {
    asm volatile(
        "mma.sync.aligned.m16n8k16.row.col.f32.f16.f16.f32 "
        "{%0,%1,%2,%3}, {%4,%5,%6,%7}, {%8,%9}, {%0,%1,%2,%3};"
        : "+f"(c[0]), "+f"(c[1]), "+f"(c[2]), "+f"(c[3])
        : "r"(a[0]), "r"(a[1]), "r"(a[2]), "r"(a[3]), "r"(b0), "r"(b1));
}

__device__ __forceinline__ void cp16(uint32_t s, const void* g) {
    asm volatile("cp.async.cg.shared.global [%0], [%1], 16;" :: "r"(s), "l"(g));
}
#define CP_COMMIT() asm volatile("cp.async.commit_group;" ::: "memory")
#define CP_WAIT1()  asm volatile("cp.async.wait_group 1;"  ::: "memory")
#define CP_WAIT0()  asm volatile("cp.async.wait_group 0;"  ::: "memory")

__device__ __forceinline__ void split_bf16(float v, bf16& h, bf16& m) {
    h = __float2bfloat16(v);
    m = __float2bfloat16(v - __bfloat162float(h));
}

// 64B-row swizzle: 16B chunk index XORed with row bits [2:1] -> conflict-free LDSM
__device__ __forceinline__ uint32_t swz64(int r, int ch) {
    return (uint32_t)(r * 64 + (((unsigned)ch ^ (((unsigned)r >> 1) & 3u)) << 4));
}

// ---------------------------------------------------------------------------
// 3-split bf16 mainloop: stage 32KB (Ah 8K, Am 8K, Bh 8K, Bm 8K), 3 stages.
// ---------------------------------------------------------------------------
#define STAGE_B    32768
#define OFF_AM     8192
#define OFF_BH     16384
#define OFF_BM     24576
#define SMEM_GEMM  (3 * STAGE_B)    // 98304

__device__ __forceinline__ void gemm_mainloop(
    uint32_t sb,
    const bf16* __restrict__ Ah, const bf16* __restrict__ Am, int lda,
    const bf16* __restrict__ Bh, const bf16* __restrict__ Bm, int ldb,
    int chunks, float (&acc)[2][8][4])
{
#pragma unroll
    for (int a = 0; a < 2; a++)
#pragma unroll
        for (int b = 0; b < 8; b++)
#pragma unroll
            for (int cc = 0; cc < 4; cc++) acc[a][b][cc] = 0.f;

    const int tid = threadIdx.x, lane = tid & 31, wid = tid >> 5;
    const int wm = wid >> 1, wn = wid & 1;

    const int rA = wm * 32 + (lane & 15);
    const int hA = lane >> 4;
    const int rB = wn * 64 + (lane & 7) + ((lane >> 4) & 1) * 8;
    const int hB = (lane >> 3) & 1;

    const int r  = tid >> 1;
    const int c0 = (tid & 1) * 2;
    const uint32_t so0 = swz64(r, c0);
    const uint32_t so1 = swz64(r, c0 + 1);
    const bf16* pAh = Ah + (size_t)r * lda + c0 * 8;
    const bf16* pAm = Am + (size_t)r * lda + c0 * 8;
    const bf16* pBh = Bh + (size_t)r * ldb + c0 * 8;
    const bf16* pBm = Bm + (size_t)r * ldb + c0 * 8;

#define ISSUE_STAGE3(SBUF) do {                         \
        const uint32_t _b = (SBUF);                     \
        cp16(_b + so0,          pAh);                   \
        cp16(_b + so1,          pAh + 8);               \
        cp16(_b + OFF_AM + so0, pAm);                   \
        cp16(_b + OFF_AM + so1, pAm + 8);               \
        cp16(_b + OFF_BH + so0, pBh);                   \
        cp16(_b + OFF_BH + so1, pBh + 8);               \
        cp16(_b + OFF_BM + so0, pBm);                   \
        cp16(_b + OFF_BM + so1, pBm + 8);               \
        pAh += 32; pAm += 32; pBh += 32; pBm += 32;     \
        CP_COMMIT();                                    \
    } while (0)

    ISSUE_STAGE3(sb);
    ISSUE_STAGE3(sb + STAGE_B);

    int stage = 0, pstage = 2;
    for (int c = 0; c < chunks; c++) {
        if (c + 1 < chunks) CP_WAIT1(); else CP_WAIT0();
        __syncthreads();
        if (c + 2 < chunks) ISSUE_STAGE3(sb + pstage * STAGE_B);
        const uint32_t buf = sb + stage * STAGE_B;
#pragma unroll
        for (int k16 = 0; k16 < 2; k16++) {
            uint32_t aH[2][4], aM[2][4];
#pragma unroll
            for (int mb = 0; mb < 2; mb++) {
                const uint32_t off = swz64(rA + mb * 16, k16 * 2 + hA);
                LDSM_X4(aH[mb], buf + off);
                LDSM_X4(aM[mb], buf + OFF_AM + off);
            }
#pragma unroll
            for (int nb = 0; nb < 4; nb++) {
                const uint32_t offB = swz64(rB + nb * 16, k16 * 2 + hB);
                uint32_t bH[4], bM[4];
                LDSM_X4(bH, buf + OFF_BH + offB);
                LDSM_X4(bM, buf + OFF_BM + offB);
#pragma unroll
                for (int mb = 0; mb < 2; mb++) {
                    mma_bf16(acc[mb][nb * 2 + 0], aH[mb], bH[0], bH[1]);
                    mma_bf16(acc[mb][nb * 2 + 1], aH[mb], bH[2], bH[3]);
                    mma_bf16(acc[mb][nb * 2 + 0], aH[mb], bM[0], bM[1]);
                    mma_bf16(acc[mb][nb * 2 + 1], aH[mb], bM[2], bM[3]);
                    mma_bf16(acc[mb][nb * 2 + 0], aM[mb], bH[0], bH[1]);
                    mma_bf16(acc[mb][nb * 2 + 1], aM[mb], bH[2], bH[3]);
                }
            }
        }
        stage = (stage == 2) ? 0 : stage + 1;
        pstage = (pstage == 2) ? 0 : pstage + 1;
    }
    __syncthreads();
#undef ISSUE_STAGE3
}

// ---------------------------------------------------------------------------
// fp16 1x1 mainloop: A single fp16, B single fp16. Stage 16KB, 3 stages.
// ---------------------------------------------------------------------------
#define STAGE11_B   16384
#define OFF11_B     8192
#define SMEM_GEMM11 (3 * STAGE11_B)   // 49152

__device__ __forceinline__ void gemm_mainloop_11(
    uint32_t sb,
    const fp16* __restrict__ A, int lda,
    const fp16* __restrict__ B, int ldb,
    int chunks, float (&acc)[2][8][4])
{
#pragma unroll
    for (int a = 0; a < 2; a++)
#pragma unroll
        for (int b = 0; b < 8; b++)
#pragma unroll
            for (int cc = 0; cc < 4; cc++) acc[a][b][cc] = 0.f;

    const int tid = threadIdx.x, lane = tid & 31, wid = tid >> 5;
    const int wm = wid >> 1, wn = wid & 1;

    const int rA = wm * 32 + (lane & 15);
    const int hA = lane >> 4;
    const int rB = wn * 64 + (lane & 7) + ((lane >> 4) & 1) * 8;
    const int hB = (lane >> 3) & 1;

    const int r  = tid >> 1;
    const int c0 = (tid & 1) * 2;
    const uint32_t so0 = swz64(r, c0);
    const uint32_t so1 = swz64(r, c0 + 1);
    const fp16* pA = A + (size_t)r * lda + c0 * 8;
    const fp16* pB = B + (size_t)r * ldb + c0 * 8;

#define ISSUE_STAGE11(SBUF) do {                        \
        const uint32_t _b = (SBUF);                     \
        cp16(_b + so0,           pA);                   \
        cp16(_b + so1,           pA + 8);               \
        cp16(_b + OFF11_B + so0, pB);                   \
        cp16(_b + OFF11_B + so1, pB + 8);               \
        pA += 32; pB += 32;                             \
        CP_COMMIT();                                    \
    } while (0)

    ISSUE_STAGE11(sb);
    ISSUE_STAGE11(sb + STAGE11_B);

    int stage = 0, pstage = 2;
    for (int c = 0; c < chunks; c++) {
        if (c + 1 < chunks) CP_WAIT1(); else CP_WAIT0();
        __syncthreads();
        if (c + 2 < chunks) ISSUE_STAGE11(sb + pstage * STAGE11_B);
        const uint32_t buf = sb + stage * STAGE11_B;
#pragma unroll
        for (int k16 = 0; k16 < 2; k16++) {
            uint32_t aV[2][4];
#pragma unroll
            for (int mb = 0; mb < 2; mb++) {
                const uint32_t off = swz64(rA + mb * 16, k16 * 2 + hA);
                LDSM_X4(aV[mb], buf + off);
            }
#pragma unroll
            for (int nb = 0; nb < 4; nb++) {
                const uint32_t offB = swz64(rB + nb * 16, k16 * 2 + hB);
                uint32_t bV[4];
                LDSM_X4(bV, buf + OFF11_B + offB);
#pragma unroll
                for (int mb = 0; mb < 2; mb++) {
                    mma_f16(acc[mb][nb * 2 + 0], aV[mb], bV[0], bV[1]);
                    mma_f16(acc[mb][nb * 2 + 1], aV[mb], bV[2], bV[3]);
                }
            }
        }
        stage = (stage == 2) ? 0 : stage + 1;
        pstage = (pstage == 2) ? 0 : pstage + 1;
    }
    __syncthreads();
#undef ISSUE_STAGE11
}

// Epilogue coordinates: acc[mb][j][reg]
//   row_local = wm*32 + mb*16 + (lane>>2) + (reg>=2)*8
//   col_local = wn*64 + j*8 + (lane&3)*2 + (reg&1)

// ---------------------------------------------------------------------------
// Kernel: ALL input conversions in one launch (flat quad index).
// ---------------------------------------------------------------------------
__global__ void __launch_bounds__(256)
k_convert_all(const float* __restrict__ hs, const float* __restrict__ wq,
              const float* __restrict__ wk, const float* __restrict__ wv,
              const float* __restrict__ wo) {
    const long NH4 = (long)MROWS * DM / 4;   // 4,194,304
    const long NW4 = (long)DM * DM / 4;      // 1,048,576
    long i = (long)blockIdx.x * blockDim.x + threadIdx.x;

    const float* src;
    long off;
    int sel;
    if (i < NH4) { src = hs; off = i; sel = 0; }
    else {
        long j = i - NH4;
        int w = (int)(j >> 20);               // NW4 == 2^20
        off = j & (NW4 - 1);
        sel = w + 1;
        src = (w == 0) ? wq : (w == 1) ? wk : (w == 2) ? wv : wo;
    }
    float4 v = ((const float4*)src)[off];
    if (sel == 4) {
        alignas(8) fp16 h[4];
        h[0] = __float2half(v.x); h[1] = __float2half(v.y);
        h[2] = __float2half(v.z); h[3] = __float2half(v.w);
        *(uint2*)(g_Wo16 + off * 4) = *(const uint2*)h;
        return;
    }
    bf16 *H, *M;
    if (sel == 0) { H = g_Hh; M = g_Hm; }
    else          { H = g_Wh3[sel - 1]; M = g_Wm3[sel - 1]; }
    alignas(8) bf16 h[4], m[4];
    split_bf16(v.x, h[0], m[0]);
    split_bf16(v.y, h[1], m[1]);
    split_bf16(v.z, h[2], m[2]);
    split_bf16(v.w, h[3], m[3]);
    *(uint2*)(H + off * 4) = *(const uint2*)h;
    *(uint2*)(M + off * 4) = *(const uint2*)m;
}

// ---------------------------------------------------------------------------
// Kernel: Q/K/V projection (bf16 3-split GEMM; Q,K -> bf16 splits, V ->
// single fp16). grid (nt, mt, which=3).
// ---------------------------------------------------------------------------
__global__ void __launch_bounds__(256, 2)
k_proj(void) {
    extern __shared__ char sm[];
    const uint32_t sb = smem_u32(sm);
    const int nt = blockIdx.x, mt = blockIdx.y, which = blockIdx.z;

    float acc[2][8][4];
    gemm_mainloop(sb,
        g_Hh + (size_t)mt * 128 * DM, g_Hm + (size_t)mt * 128 * DM, DM,
        g_Wh3[which] + (size_t)nt * 128 * DM, g_Wm3[which] + (size_t)nt * 128 * DM, DM,
        DM / 32, acc);

    const int tid = threadIdx.x, lane = tid & 31, wid = tid >> 5;
    const int wm = wid >> 1, wn = wid & 1;

    if (which == 2) {  // V -> single fp16
#pragma unroll
        for (int mb = 0; mb < 2; mb++)
#pragma unroll
            for (int rp = 0; rp < 2; rp++) {
                const int m = mt * 128 + wm * 32 + mb * 16 + (lane >> 2) + rp * 8;
                const int b = m >> 11, s = m & (SEQ - 1);
                fp16* pv = g_V16 + ((size_t)(b * NH + nt) * SEQ + s) * DH;
#pragma unroll
                for (int j = 0; j < 8; j++) {
                    const int col = wn * 64 + j * 8 + (lane & 3) * 2;
                    __half2 hv = __floats2half2_rn(acc[mb][j][rp * 2 + 0],
                                                   acc[mb][j][rp * 2 + 1]);
                    *(__half2*)(pv + col) = hv;
                }
            }
        return;
    }

    bf16* Gh = (which == 0) ? g_Qh : g_Kh;
    bf16* Gm = (which == 0) ? g_Qm : g_Km;
#pragma unroll
    for (int mb = 0; mb < 2; mb++)
#pragma unroll
        for (int rp = 0; rp < 2; rp++) {
            const int m = mt * 128 + wm * 32 + mb * 16 + (lane >> 2) + rp * 8;
            const int b = m >> 11, s = m & (SEQ - 1);
            bf16* ph = Gh + ((size_t)(b * NH + nt) * SEQ + s) * DH;
            bf16* pm = Gm + ((size_t)(b * NH + nt) * SEQ + s) * DH;
#pragma unroll
            for (int j = 0; j < 8; j++) {
                const int col = wn * 64 + j * 8 + (lane & 3) * 2;
                bf16 h0, m0, h1, m1;
                split_bf16(acc[mb][j][rp * 2 + 0], h0, m0);
                split_bf16(acc[mb][j][rp * 2 + 1], h1, m1);
                *(__nv_bfloat162*)(ph + col) = __nv_bfloat162(h0, h1);
                *(__nv_bfloat162*)(pm + col) = __nv_bfloat162(m0, m1);
            }
        }
}

// ---------------------------------------------------------------------------
// Kernel: transpose V [bh,s,dh] -> [bh,dh,s] (single fp16)
// ---------------------------------------------------------------------------
__global__ void __launch_bounds__(256)
k_transpose() {
    __shared__ fp16 tile[32][33];
    const int d0 = blockIdx.x * 32;
    const int s0 = blockIdx.y * 32;
    const int bh = blockIdx.z;
    const int tx = threadIdx.x, ty = threadIdx.y;
#pragma unroll
    for (int r = 0; r < 4; r++)
        tile[ty + r * 8][tx] =
            g_V16[(size_t)bh * SEQ * DH + (size_t)(s0 + ty + r * 8) * DH + d0 + tx];
    __syncthreads();
#pragma unroll
    for (int r = 0; r < 4; r++)
        g_Vt16[(size_t)bh * DH * SEQ + (size_t)(d0 + ty + r * 8) * SEQ + s0 + tx] =
            tile[tx][ty + r * 8];
}

// ---------------------------------------------------------------------------
// Kernel: causal scores = Q . K^T (fp32 to g_S). Triangular launch.
// ---------------------------------------------------------------------------
__global__ void __launch_bounds__(256, 2)
k_scores() {
    const int t = blockIdx.x;
    int bi = (int)((sqrtf(8.f * (float)t + 1.f) - 1.f) * 0.5f);
    if ((bi + 1) * (bi + 2) / 2 <= t) bi++;
    else if (bi * (bi + 1) / 2 > t) bi--;
    const int bj = t - bi * (bi + 1) / 2;
    const int bh = blockIdx.y;

    extern __shared__ char sm[];
    const uint32_t sb = smem_u32(sm);

    const size_t hb = (size_t)bh * SEQ * DH;
    float acc[2][8][4];
    gemm_mainloop(sb,
        g_Qh + hb + (size_t)bi * 128 * DH, g_Qm + hb + (size_t)bi * 128 * DH, DH,
        g_Kh + hb + (size_t)bj * 128 * DH, g_Km + hb + (size_t)bj * 128 * DH, DH,
        DH / 32, acc);

    const int tid = threadIdx.x, lane = tid & 31, wid = tid >> 5;
    const int wm = wid >> 1, wn = wid & 1;
    float* Sp = g_S + (size_t)bh * SEQ * SEQ;
#pragma unroll
    for (int mb = 0; mb < 2; mb++)
#pragma unroll
        for (int rp = 0; rp < 2; rp++) {
            const int m = bi * 128 + wm * 32 + mb * 16 + (lane >> 2) + rp * 8;
            float* dst = Sp + (size_t)m * SEQ + bj * 128;
#pragma unroll
            for (int j = 0; j < 8; j++) {
                const int col = wn * 64 + j * 8 + (lane & 3) * 2;
                *(float2*)(dst + col) =
                    make_float2(acc[mb][j][rp * 2], acc[mb][j][rp * 2 + 1]);
            }
        }
}

// ---------------------------------------------------------------------------
// Kernel: row softmax (vectorized, causal-skipped loads). In-place single
// fp16 probs into the g_S row; fp32 probs to Pext when use_ext.
// ---------------------------------------------------------------------------
__device__ __forceinline__ float warp_max(float v) {
#pragma unroll
    for (int o = 16; o > 0; o >>= 1) v = fmaxf(v, __shfl_xor_sync(0xffffffffu, v, o));
    return v;
}
__device__ __forceinline__ float warp_sum(float v) {
#pragma unroll
    for (int o = 16; o > 0; o >>= 1) v += __shfl_xor_sync(0xffffffffu, v, o);
    return v;
}

__global__ void __launch_bounds__(256)
k_softmax(float* __restrict__ Pext, int use_ext) {
    __shared__ float shm[8];
    __shared__ float shs[8];

    const size_t row = blockIdx.x;
    const int q = (int)(row & (SEQ - 1));
    const float* pr = g_S + row * (size_t)SEQ;
    const int tid = threadIdx.x;
    const int wid = tid >> 5, lid = tid & 31;
    const int jb = tid * 8;

    float v[8];
    if (jb <= q) {
        float4 a = *(const float4*)(pr + jb);
        float4 b = *(const float4*)(pr + jb + 4);
        v[0] = a.x; v[1] = a.y; v[2] = a.z; v[3] = a.w;
        v[4] = b.x; v[5] = b.y; v[6] = b.z; v[7] = b.w;
#pragma unroll
        for (int k = 0; k < 8; k++)
            if (jb + k > q) v[k] = -CUDART_INF_F;
    } else {
#pragma unroll
        for (int k = 0; k < 8; k++) v[k] = -CUDART_INF_F;
    }
    float m = -CUDART_INF_F;
#pragma unroll
    for (int k = 0; k < 8; k++) m = fmaxf(m, v[k]);
    m = warp_max(m);
    if (lid == 0) shm[wid] = m;
    __syncthreads();          // all row reads precede in-place writes
    if (tid < 32) {
        float t = (tid < 8) ? shm[tid] : -CUDART_INF_F;
        t = warp_max(t);
        if (tid == 0) shm[0] = t;
    }
    __syncthreads();
    m = shm[0];

    float s = 0.f;
#pragma unroll
    for (int k = 0; k < 8; k++) {
        const float e = expf(v[k] - m);
        v[k] = e;
        s += e;
    }
    s = warp_sum(s);
    if (lid == 0) shs[wid] = s;
    __syncthreads();
    if (tid < 32) {
        float t = (tid < 8) ? shs[tid] : 0.f;
        t = warp_sum(t);
        if (tid == 0) shs[0] = t;
    }
    __syncthreads();
    const float inv = 1.f / shs[0];

#pragma unroll
    for (int k = 0; k < 8; k++) v[k] *= inv;

    if (use_ext) {
        float* po = Pext + row * (size_t)SEQ + jb;
        *(float4*)(po)     = make_float4(v[0], v[1], v[2], v[3]);
        *(float4*)(po + 4) = make_float4(v[4], v[5], v[6], v[7]);
    }

    const int jmax = ((q >> 7) + 1) << 7;      // 128-aligned
    if (jb < jmax) {
        fp16* ph = (fp16*)(g_S) + row * (size_t)(2 * SEQ) + jb;  // row = 8KB
        alignas(16) fp16 h[8];
#pragma unroll
        for (int k = 0; k < 8; k++) h[k] = __float2half(v[k]);
        *(uint4*)ph = *(const uint4*)h;
    }
}

// ---------------------------------------------------------------------------
// Kernel: AV = P . V (fp16 single x single, causal-truncated).
// grid (bh=64, ybi=16), longest-first. Epilogue: single fp16 into g_AO16.
// ---------------------------------------------------------------------------
__global__ void __launch_bounds__(256, 2)
k_av() {
    const int bh = blockIdx.x;
    const int bi = 15 - (int)blockIdx.y;
    extern __shared__ char sm[];
    const uint32_t sb = smem_u32(sm);

    const fp16* Pbase = (const fp16*)(g_S) +
                        (size_t)(bh * SEQ + bi * 128) * (size_t)(2 * SEQ);

    float acc[2][8][4];
    gemm_mainloop_11(sb,
        Pbase, 2 * SEQ,
        g_Vt16 + (size_t)bh * DH * SEQ, SEQ,
        (bi + 1) * 4, acc);

    const int tid = threadIdx.x, lane = tid & 31, wid = tid >> 5;
    const int wm = wid >> 1, wn = wid & 1;
    const int b = bh >> 4, h = bh & 15;
#pragma unroll
    for (int mb = 0; mb < 2; mb++)
#pragma unroll
        for (int rp = 0; rp < 2; rp++) {
            const int s = bi * 128 + wm * 32 + mb * 16 + (lane >> 2) + rp * 8;
            fp16* po = g_AO16 + ((size_t)(b * SEQ + s)) * DM + h * 128;
#pragma unroll
            for (int j = 0; j < 8; j++) {
                const int col = wn * 64 + j * 8 + (lane & 3) * 2;
                __half2 hv = __floats2half2_rn(acc[mb][j][rp * 2 + 0],
                                               acc[mb][j][rp * 2 + 1]);
                *(__half2*)(po + col) = hv;
            }
        }
}

// ---------------------------------------------------------------------------
// Kernel: out = AO . Wo^T + bo (fp16 single x single, fp32 to d_out).
// ---------------------------------------------------------------------------
__global__ void __launch_bounds__(256, 2)
k_out(const float* __restrict__ bias, float* __restrict__ Out) {
    extern __shared__ char sm[];
    const uint32_t sb = smem_u32(sm);
    const int nt = blockIdx.x, mt = blockIdx.y;

    float acc[2][8][4];
    gemm_mainloop_11(sb,
        g_AO16 + (size_t)mt * 128 * DM, DM,
        g_Wo16 + (size_t)nt * 128 * DM, DM,
        DM / 32, acc);

    const int tid = threadIdx.x, lane = tid & 31, wid = tid >> 5;
    const int wm = wid >> 1, wn = wid & 1;
#pragma unroll
    for (int mb = 0; mb < 2; mb++)
#pragma unroll
        for (int rp = 0; rp < 2; rp++) {
            const int m = mt * 128 + wm * 32 + mb * 16 + (lane >> 2) + rp * 8;
            float* dst = Out + (size_t)m * DM + nt * 128;
#pragma unroll
            for (int j = 0; j < 8; j++) {
                const int col = wn * 64 + j * 8 + (lane & 3) * 2;
                *(float2*)(dst + col) =
                    make_float2(acc[mb][j][rp * 2] + bias[nt * 128 + col],
                                acc[mb][j][rp * 2 + 1] + bias[nt * 128 + col + 1]);
            }
        }
}

// ---------------------------------------------------------------------------
// Launch
// ---------------------------------------------------------------------------
extern "C" void kernel_launch(void* const* d_in, const int* in_sizes, int n_in,
                              void* d_out, int out_size) {
    const float* hs = (const float*)d_in[0];
    const float* wq = (const float*)d_in[1];
    const float* wk = (const float*)d_in[2];
    const float* wv = (const float*)d_in[3];
    const float* wo = (const float*)d_in[4];
    const float* bo = (const float*)d_in[5];
    float* out = (float*)d_out;

    const long long OUT_ELEMS = (long long)MROWS * DM;       // 16,777,216
    const long long WEI_ELEMS = (long long)BH * SEQ * SEQ;   // 268,435,456
    const int use_ext = ((long long)out_size >= OUT_ELEMS + WEI_ELEMS) ? 1 : 0;
    float* Pext = use_ext ? (out + OUT_ELEMS) : nullptr;

    cudaFuncSetAttribute(k_proj,   cudaFuncAttributeMaxDynamicSharedMemorySize, SMEM_GEMM);
    cudaFuncSetAttribute(k_scores, cudaFuncAttributeMaxDynamicSharedMemorySize, SMEM_GEMM);
    cudaFuncSetAttribute(k_av,     cudaFuncAttributeMaxDynamicSharedMemorySize, SMEM_GEMM11);
    cudaFuncSetAttribute(k_out,    cudaFuncAttributeMaxDynamicSharedMemorySize, SMEM_GEMM11);

    const long NH4 = (long)MROWS * DM / 4;   // 4,194,304
    const long NW4 = (long)DM * DM / 4;      // 1,048,576
    const long totq = NH4 + 4 * NW4;         // 8,388,608
    k_convert_all<<<(unsigned)((totq + 255) / 256), 256>>>(hs, wq, wk, wv, wo);

    k_proj<<<dim3(16, 64, 3), 256, SMEM_GEMM>>>();

    k_transpose<<<dim3(4, 64, BH), dim3(32, 8)>>>();

    k_scores<<<dim3(136, BH), 256, SMEM_GEMM>>>();
    k_softmax<<<BH * SEQ, 256>>>(Pext, use_ext);
    k_av<<<dim3(BH, 16), 256, SMEM_GEMM11>>>();
    k_out<<<dim3(16, 64), 256, SMEM_GEMM11>>>(bo, out);
}

// round 17
// speedup vs baseline: 1.0608x; 1.0537x over previous
#include <cuda_runtime.h>
#include <cuda_bf16.h>
#include <cuda_fp16.h>
#include <math_constants.h>
#include <cstdint>
#include <cstddef>

#define BATCH 4
#define NH    16
#define SEQ   2048
#define DH    128
#define DM    2048
#define BH    (BATCH*NH)     // 64
#define MROWS (BATCH*SEQ)    // 8192

typedef __nv_bfloat16 bf16;
typedef __half fp16;

// ---------------------------------------------------------------------------
// Device scratch (static globals; total ~1.50 GB < 2 GB x86 link limit)
// ---------------------------------------------------------------------------
__device__ bf16 g_Hh[(size_t)MROWS * DM];        // hidden bf16 hi   (Q,K proj)
__device__ bf16 g_Hm[(size_t)MROWS * DM];        // hidden bf16 mid
__device__ fp16 g_Hh16[(size_t)MROWS * DM];      // hidden fp16 hi   (V proj)
__device__ fp16 g_Hm16[(size_t)MROWS * DM];      // hidden fp16 mid
__device__ bf16 g_Wh3[3][(size_t)DM * DM];       // wq, wk ([2] unused)
__device__ bf16 g_Wm3[3][(size_t)DM * DM];
__device__ fp16 g_Wv16[(size_t)DM * DM];         // wv single fp16
__device__ fp16 g_Wo16[(size_t)DM * DM];         // wo single fp16
__device__ bf16 g_Qh[(size_t)BH * SEQ * DH];
__device__ bf16 g_Qm[(size_t)BH * SEQ * DH];
__device__ bf16 g_Kh[(size_t)BH * SEQ * DH];
__device__ bf16 g_Km[(size_t)BH * SEQ * DH];
__device__ fp16 g_V16[(size_t)BH * SEQ * DH];    // V single fp16 [bh,s,dh]
__device__ fp16 g_Vt16[(size_t)BH * DH * SEQ];   // V^T single fp16 [bh,dh,s]
// g_S: 1 GiB. fp32 scores; softmax overwrites each 8KB row IN PLACE with
// SINGLE fp16 probs at fp16 offsets [0,2048) (row stride 4096 fp16).
__device__ float g_S[(size_t)BH * SEQ * SEQ];
__device__ fp16 g_AO16[(size_t)MROWS * DM];      // attn-out single fp16

// ---------------------------------------------------------------------------
// PTX helpers (sm_80-era: mma.sync / ldmatrix / cp.async — valid on sm_100)
// ---------------------------------------------------------------------------
__device__ __forceinline__ uint32_t smem_u32(const void* p) {
    uint32_t a;
    asm("{ .reg .u64 t; cvta.to.shared.u64 t, %1; cvt.u32.u64 %0, t; }"
        : "=r"(a) : "l"(p));
    return a;
}

#define LDSM_X4(R, addr) \
    asm volatile("ldmatrix.sync.aligned.m8n8.x4.shared.b16 {%0,%1,%2,%3}, [%4];" \
                 : "=r"((R)[0]), "=r"((R)[1]), "=r"((R)[2]), "=r"((R)[3]) : "r"(addr))

__device__ __forceinline__ void mma_bf16(float* c, const uint32_t* a,
                                         uint32_t b0, uint32_t b1) {
    asm volatile(
        "mma.sync.aligned.m16n8k16.row.col.f32.bf16.bf16.f32 "
        "{%0,%1,%2,%3}, {%4,%5,%6,%7}, {%8,%9}, {%0,%1,%2,%3};"
        : "+f"(c[0]), "+f"(c[1]), "+f"(c[2]), "+f"(c[3])
        : "r"(a[0]), "r"(a[1]), "r"(a[2]), "r"(a[3]), "r"(b0), "r"(b1));
}

__device__ __forceinline__ void mma_f16(float* c, const uint32_t* a,
                                        uint32_t b0, uint32_t b1) {
    asm volatile(
        "mma.sync.aligned.m16n8k16.row.col.f32.f16.f16.f32 "
        "{%0,%1,%2,%3}, {%4,%5,%6,%7}, {%8,%9}, {%0,%1,%2,%3};"
        : "+f"(c[0]), "+f"(c[1]), "+f"(c[2]), "+f"(c[3])
        : "r"(a[0]), "r"(a[1]), "r"(a[2]), "r"(a[3]), "r"(b0), "r"(b1));
}

__device__ __forceinline__ void cp16(uint32_t s, const void* g) {
    asm volatile("cp.async.cg.shared.global [%0], [%1], 16;" :: "r"(s), "l"(g));
}
#define CP_COMMIT() asm volatile("cp.async.commit_group;" ::: "memory")
#define CP_WAIT1()  asm volatile("cp.async.wait_group 1;"  ::: "memory")
#define CP_WAIT0()  asm volatile("cp.async.wait_group 0;"  ::: "memory")

__device__ __forceinline__ void split_bf16(float v, bf16& h, bf16& m) {
    h = __float2bfloat16(v);
    m = __float2bfloat16(v - __bfloat162float(h));
}
__device__ __forceinline__ void split_f16(float v, fp16& h, fp16& m) {
    h = __float2half(v);
    m = __float2half(v - __half2float(h));
}

// 64B-row swizzle: 16B chunk index XORed with row bits [2:1] -> conflict-free LDSM
__device__ __forceinline__ uint32_t swz64(int r, int ch) {
    return (uint32_t)(r * 64 + (((unsigned)ch ^ (((unsigned)r >> 1) & 3u)) << 4));
}

// ---------------------------------------------------------------------------
// 3-split bf16 mainloop: stage 32KB (Ah 8K, Am 8K, Bh 8K, Bm 8K), 3 stages.
// ---------------------------------------------------------------------------
#define STAGE_B    32768
#define OFF_AM     8192
#define OFF_BH     16384
#define OFF_BM     24576
#define SMEM_GEMM  (3 * STAGE_B)    // 98304

__device__ __forceinline__ void gemm_mainloop(
    uint32_t sb,
    const bf16* __restrict__ Ah, const bf16* __restrict__ Am, int lda,
    const bf16* __restrict__ Bh, const bf16* __restrict__ Bm, int ldb,
    int chunks, float (&acc)[2][8][4])
{
#pragma unroll
    for (int a = 0; a < 2; a++)
#pragma unroll
        for (int b = 0; b < 8; b++)
#pragma unroll
            for (int cc = 0; cc < 4; cc++) acc[a][b][cc] = 0.f;

    const int tid = threadIdx.x, lane = tid & 31, wid = tid >> 5;
    const int wm = wid >> 1, wn = wid & 1;

    const int rA = wm * 32 + (lane & 15);
    const int hA = lane >> 4;
    const int rB = wn * 64 + (lane & 7) + ((lane >> 4) & 1) * 8;
    const int hB = (lane >> 3) & 1;

    const int r  = tid >> 1;
    const int c0 = (tid & 1) * 2;
    const uint32_t so0 = swz64(r, c0);
    const uint32_t so1 = swz64(r, c0 + 1);
    const bf16* pAh = Ah + (size_t)r * lda + c0 * 8;
    const bf16* pAm = Am + (size_t)r * lda + c0 * 8;
    const bf16* pBh = Bh + (size_t)r * ldb + c0 * 8;
    const bf16* pBm = Bm + (size_t)r * ldb + c0 * 8;

#define ISSUE_STAGE3(SBUF) do {                         \
        const uint32_t _b = (SBUF);                     \
        cp16(_b + so0,          pAh);                   \
        cp16(_b + so1,          pAh + 8);               \
        cp16(_b + OFF_AM + so0, pAm);                   \
        cp16(_b + OFF_AM + so1, pAm + 8);               \
        cp16(_b + OFF_BH + so0, pBh);                   \
        cp16(_b + OFF_BH + so1, pBh + 8);               \
        cp16(_b + OFF_BM + so0, pBm);                   \
        cp16(_b + OFF_BM + so1, pBm + 8);               \
        pAh += 32; pAm += 32; pBh += 32; pBm += 32;     \
        CP_COMMIT();                                    \
    } while (0)

    ISSUE_STAGE3(sb);
    ISSUE_STAGE3(sb + STAGE_B);

    int stage = 0, pstage = 2;
    for (int c = 0; c < chunks; c++) {
        if (c + 1 < chunks) CP_WAIT1(); else CP_WAIT0();
        __syncthreads();
        if (c + 2 < chunks) ISSUE_STAGE3(sb + pstage * STAGE_B);
        const uint32_t buf = sb + stage * STAGE_B;
#pragma unroll
        for (int k16 = 0; k16 < 2; k16++) {
            uint32_t aH[2][4], aM[2][4];
#pragma unroll
            for (int mb = 0; mb < 2; mb++) {
                const uint32_t off = swz64(rA + mb * 16, k16 * 2 + hA);
                LDSM_X4(aH[mb], buf + off);
                LDSM_X4(aM[mb], buf + OFF_AM + off);
            }
#pragma unroll
            for (int nb = 0; nb < 4; nb++) {
                const uint32_t offB = swz64(rB + nb * 16, k16 * 2 + hB);
                uint32_t bH[4], bM[4];
                LDSM_X4(bH, buf + OFF_BH + offB);
                LDSM_X4(bM, buf + OFF_BM + offB);
#pragma unroll
                for (int mb = 0; mb < 2; mb++) {
                    mma_bf16(acc[mb][nb * 2 + 0], aH[mb], bH[0], bH[1]);
                    mma_bf16(acc[mb][nb * 2 + 1], aH[mb], bH[2], bH[3]);
                    mma_bf16(acc[mb][nb * 2 + 0], aH[mb], bM[0], bM[1]);
                    mma_bf16(acc[mb][nb * 2 + 1], aH[mb], bM[2], bM[3]);
                    mma_bf16(acc[mb][nb * 2 + 0], aM[mb], bH[0], bH[1]);
                    mma_bf16(acc[mb][nb * 2 + 1], aM[mb], bH[2], bH[3]);
                }
            }
        }
        stage = (stage == 2) ? 0 : stage + 1;
        pstage = (pstage == 2) ? 0 : pstage + 1;
    }
    __syncthreads();
#undef ISSUE_STAGE3
}

// ---------------------------------------------------------------------------
// fp16 2x1 mainloop: A = Ah+Am (fp16 2-split), B single fp16. 2 MMAs/step.
// Stage 24KB (Ah 8K, Am 8K, B 8K), 3 stages. (Proven in round 9.)
// ---------------------------------------------------------------------------
#define STAGE21_B   24576
#define OFF21_AM    8192
#define OFF21_B     16384
#define SMEM_GEMM21 (3 * STAGE21_B)   // 73728 (< SMEM_GEMM)

__device__ __forceinline__ void gemm_mainloop_21(
    uint32_t sb,
    const fp16* __restrict__ Ah, const fp16* __restrict__ Am, int lda,
    const fp16* __restrict__ B, int ldb,
    int chunks, float (&acc)[2][8][4])
{
#pragma unroll
    for (int a = 0; a < 2; a++)
#pragma unroll
        for (int b = 0; b < 8; b++)
#pragma unroll
            for (int cc = 0; cc < 4; cc++) acc[a][b][cc] = 0.f;

    const int tid = threadIdx.x, lane = tid & 31, wid = tid >> 5;
    const int wm = wid >> 1, wn = wid & 1;

    const int rA = wm * 32 + (lane & 15);
    const int hA = lane >> 4;
    const int rB = wn * 64 + (lane & 7) + ((lane >> 4) & 1) * 8;
    const int hB = (lane >> 3) & 1;

    const int r  = tid >> 1;
    const int c0 = (tid & 1) * 2;
    const uint32_t so0 = swz64(r, c0);
    const uint32_t so1 = swz64(r, c0 + 1);
    const fp16* pAh = Ah + (size_t)r * lda + c0 * 8;
    const fp16* pAm = Am + (size_t)r * lda + c0 * 8;
    const fp16* pB  = B  + (size_t)r * ldb + c0 * 8;

#define ISSUE_STAGE21(SBUF) do {                        \
        const uint32_t _b = (SBUF);                     \
        cp16(_b + so0,            pAh);                 \
        cp16(_b + so1,            pAh + 8);             \
        cp16(_b + OFF21_AM + so0, pAm);                 \
        cp16(_b + OFF21_AM + so1, pAm + 8);             \
        cp16(_b + OFF21_B + so0,  pB);                  \
        cp16(_b + OFF21_B + so1,  pB + 8);              \
        pAh += 32; pAm += 32; pB += 32;                 \
        CP_COMMIT();                                    \
    } while (0)

    ISSUE_STAGE21(sb);
    ISSUE_STAGE21(sb + STAGE21_B);

    int stage = 0, pstage = 2;
    for (int c = 0; c < chunks; c++) {
        if (c + 1 < chunks) CP_WAIT1(); else CP_WAIT0();
        __syncthreads();
        if (c + 2 < chunks) ISSUE_STAGE21(sb + pstage * STAGE21_B);
        const uint32_t buf = sb + stage * STAGE21_B;
#pragma unroll
        for (int k16 = 0; k16 < 2; k16++) {
            uint32_t aH[2][4], aM[2][4];
#pragma unroll
            for (int mb = 0; mb < 2; mb++) {
                const uint32_t off = swz64(rA + mb * 16, k16 * 2 + hA);
                LDSM_X4(aH[mb], buf + off);
                LDSM_X4(aM[mb], buf + OFF21_AM + off);
            }
#pragma unroll
            for (int nb = 0; nb < 4; nb++) {
                const uint32_t offB = swz64(rB + nb * 16, k16 * 2 + hB);
                uint32_t bV[4];
                LDSM_X4(bV, buf + OFF21_B + offB);
#pragma unroll
                for (int mb = 0; mb < 2; mb++) {
                    mma_f16(acc[mb][nb * 2 + 0], aH[mb], bV[0], bV[1]);
                    mma_f16(acc[mb][nb * 2 + 1], aH[mb], bV[2], bV[3]);
                    mma_f16(acc[mb][nb * 2 + 0], aM[mb], bV[0], bV[1]);
                    mma_f16(acc[mb][nb * 2 + 1], aM[mb], bV[2], bV[3]);
                }
            }
        }
        stage = (stage == 2) ? 0 : stage + 1;
        pstage = (pstage == 2) ? 0 : pstage + 1;
    }
    __syncthreads();
#undef ISSUE_STAGE21
}

// ---------------------------------------------------------------------------
// fp16 1x1 mainloop: A single fp16, B single fp16. Stage 16KB, 3 stages.
// ---------------------------------------------------------------------------
#define STAGE11_B   16384
#define OFF11_B     8192
#define SMEM_GEMM11 (3 * STAGE11_B)   // 49152

__device__ __forceinline__ void gemm_mainloop_11(
    uint32_t sb,
    const fp16* __restrict__ A, int lda,
    const fp16* __restrict__ B, int ldb,
    int chunks, float (&acc)[2][8][4])
{
#pragma unroll
    for (int a = 0; a < 2; a++)
#pragma unroll
        for (int b = 0; b < 8; b++)
#pragma unroll
            for (int cc = 0; cc < 4; cc++) acc[a][b][cc] = 0.f;

    const int tid = threadIdx.x, lane = tid & 31, wid = tid >> 5;
    const int wm = wid >> 1, wn = wid & 1;

    const int rA = wm * 32 + (lane & 15);
    const int hA = lane >> 4;
    const int rB = wn * 64 + (lane & 7) + ((lane >> 4) & 1) * 8;
    const int hB = (lane >> 3) & 1;

    const int r  = tid >> 1;
    const int c0 = (tid & 1) * 2;
    const uint32_t so0 = swz64(r, c0);
    const uint32_t so1 = swz64(r, c0 + 1);
    const fp16* pA = A + (size_t)r * lda + c0 * 8;
    const fp16* pB = B + (size_t)r * ldb + c0 * 8;

#define ISSUE_STAGE11(SBUF) do {                        \
        const uint32_t _b = (SBUF);                     \
        cp16(_b + so0,           pA);                   \
        cp16(_b + so1,           pA + 8);               \
        cp16(_b + OFF11_B + so0, pB);                   \
        cp16(_b + OFF11_B + so1, pB + 8);               \
        pA += 32; pB += 32;                             \
        CP_COMMIT();                                    \
    } while (0)

    ISSUE_STAGE11(sb);
    ISSUE_STAGE11(sb + STAGE11_B);

    int stage = 0, pstage = 2;
    for (int c = 0; c < chunks; c++) {
        if (c + 1 < chunks) CP_WAIT1(); else CP_WAIT0();
        __syncthreads();
        if (c + 2 < chunks) ISSUE_STAGE11(sb + pstage * STAGE11_B);
        const uint32_t buf = sb + stage * STAGE11_B;
#pragma unroll
        for (int k16 = 0; k16 < 2; k16++) {
            uint32_t aV[2][4];
#pragma unroll
            for (int mb = 0; mb < 2; mb++) {
                const uint32_t off = swz64(rA + mb * 16, k16 * 2 + hA);
                LDSM_X4(aV[mb], buf + off);
            }
#pragma unroll
            for (int nb = 0; nb < 4; nb++) {
                const uint32_t offB = swz64(rB + nb * 16, k16 * 2 + hB);
                uint32_t bV[4];
                LDSM_X4(bV, buf + OFF11_B + offB);
#pragma unroll
                for (int mb = 0; mb < 2; mb++) {
                    mma_f16(acc[mb][nb * 2 + 0], aV[mb], bV[0], bV[1]);
                    mma_f16(acc[mb][nb * 2 + 1], aV[mb], bV[2], bV[3]);
                }
            }
        }
        stage = (stage == 2) ? 0 : stage + 1;
        pstage = (pstage == 2) ? 0 : pstage + 1;
    }
    __syncthreads();
#undef ISSUE_STAGE11
}

// Epilogue coordinates: acc[mb][j][reg]
//   row_local = wm*32 + mb*16 + (lane>>2) + (reg>=2)*8
//   col_local = wn*64 + j*8 + (lane&3)*2 + (reg&1)

// ---------------------------------------------------------------------------
// Kernel: ALL input conversions in one launch (flat quad index).
// hidden -> bf16 splits AND fp16 splits; wq,wk -> bf16 splits;
// wv, wo -> single fp16.
// ---------------------------------------------------------------------------
__global__ void __launch_bounds__(256)
k_convert_all(const float* __restrict__ hs, const float* __restrict__ wq,
              const float* __restrict__ wk, const float* __restrict__ wv,
              const float* __restrict__ wo) {
    const long NH4 = (long)MROWS * DM / 4;   // 4,194,304
    const long NW4 = (long)DM * DM / 4;      // 1,048,576
    long i = (long)blockIdx.x * blockDim.x + threadIdx.x;

    if (i < NH4) {
        float4 v = ((const float4*)hs)[i];
        alignas(8) bf16 h[4], m[4];
        alignas(8) fp16 h16[4], m16[4];
#pragma unroll
        for (int k = 0; k < 4; k++) {
            const float f = (&v.x)[k];
            split_bf16(f, h[k], m[k]);
            split_f16(f, h16[k], m16[k]);
        }
        *(uint2*)(g_Hh + i * 4)   = *(const uint2*)h;
        *(uint2*)(g_Hm + i * 4)   = *(const uint2*)m;
        *(uint2*)(g_Hh16 + i * 4) = *(const uint2*)h16;
        *(uint2*)(g_Hm16 + i * 4) = *(const uint2*)m16;
        return;
    }
    long j = i - NH4;
    int w = (int)(j >> 20);               // NW4 == 2^20
    long off = j & (NW4 - 1);
    const float* src = (w == 0) ? wq : (w == 1) ? wk : (w == 2) ? wv : wo;
    float4 v = ((const float4*)src)[off];
    if (w >= 2) {                          // wv, wo -> single fp16
        fp16* dst = (w == 2) ? g_Wv16 : g_Wo16;
        alignas(8) fp16 h[4];
        h[0] = __float2half(v.x); h[1] = __float2half(v.y);
        h[2] = __float2half(v.z); h[3] = __float2half(v.w);
        *(uint2*)(dst + off * 4) = *(const uint2*)h;
        return;
    }
    bf16* H = g_Wh3[w];
    bf16* M = g_Wm3[w];
    alignas(8) bf16 h[4], m[4];
    split_bf16(v.x, h[0], m[0]);
    split_bf16(v.y, h[1], m[1]);
    split_bf16(v.z, h[2], m[2]);
    split_bf16(v.w, h[3], m[3]);
    *(uint2*)(H + off * 4) = *(const uint2*)h;
    *(uint2*)(M + off * 4) = *(const uint2*)m;
}

// ---------------------------------------------------------------------------
// Kernel: Q/K/V projection. Q,K: bf16 3-split GEMM -> bf16 split outputs.
// V: fp16 2x1 GEMM ((Hh16+Hm16) x Wv16) -> single fp16 output.
// grid (nt, mt, which=3).
// ---------------------------------------------------------------------------
__global__ void __launch_bounds__(256, 2)
k_proj(void) {
    extern __shared__ char sm[];
    const uint32_t sb = smem_u32(sm);
    const int nt = blockIdx.x, mt = blockIdx.y, which = blockIdx.z;

    const int tid = threadIdx.x, lane = tid & 31, wid = tid >> 5;
    const int wm = wid >> 1, wn = wid & 1;

    float acc[2][8][4];

    if (which == 2) {  // V projection: fp16 2x1, epilogue single fp16
        gemm_mainloop_21(sb,
            g_Hh16 + (size_t)mt * 128 * DM, g_Hm16 + (size_t)mt * 128 * DM, DM,
            g_Wv16 + (size_t)nt * 128 * DM, DM,
            DM / 32, acc);
#pragma unroll
        for (int mb = 0; mb < 2; mb++)
#pragma unroll
            for (int rp = 0; rp < 2; rp++) {
                const int m = mt * 128 + wm * 32 + mb * 16 + (lane >> 2) + rp * 8;
                const int b = m >> 11, s = m & (SEQ - 1);
                fp16* pv = g_V16 + ((size_t)(b * NH + nt) * SEQ + s) * DH;
#pragma unroll
                for (int j = 0; j < 8; j++) {
                    const int col = wn * 64 + j * 8 + (lane & 3) * 2;
                    __half2 hv = __floats2half2_rn(acc[mb][j][rp * 2 + 0],
                                                   acc[mb][j][rp * 2 + 1]);
                    *(__half2*)(pv + col) = hv;
                }
            }
        return;
    }

    gemm_mainloop(sb,
        g_Hh + (size_t)mt * 128 * DM, g_Hm + (size_t)mt * 128 * DM, DM,
        g_Wh3[which] + (size_t)nt * 128 * DM, g_Wm3[which] + (size_t)nt * 128 * DM, DM,
        DM / 32, acc);

    bf16* Gh = (which == 0) ? g_Qh : g_Kh;
    bf16* Gm = (which == 0) ? g_Qm : g_Km;
#pragma unroll
    for (int mb = 0; mb < 2; mb++)
#pragma unroll
        for (int rp = 0; rp < 2; rp++) {
            const int m = mt * 128 + wm * 32 + mb * 16 + (lane >> 2) + rp * 8;
            const int b = m >> 11, s = m & (SEQ - 1);
            bf16* ph = Gh + ((size_t)(b * NH + nt) * SEQ + s) * DH;
            bf16* pm = Gm + ((size_t)(b * NH + nt) * SEQ + s) * DH;
#pragma unroll
            for (int j = 0; j < 8; j++) {
                const int col = wn * 64 + j * 8 + (lane & 3) * 2;
                bf16 h0, m0, h1, m1;
                split_bf16(acc[mb][j][rp * 2 + 0], h0, m0);
                split_bf16(acc[mb][j][rp * 2 + 1], h1, m1);
                *(__nv_bfloat162*)(ph + col) = __nv_bfloat162(h0, h1);
                *(__nv_bfloat162*)(pm + col) = __nv_bfloat162(m0, m1);
            }
        }
}

// ---------------------------------------------------------------------------
// Kernel: transpose V [bh,s,dh] -> [bh,dh,s] (single fp16)
// ---------------------------------------------------------------------------
__global__ void __launch_bounds__(256)
k_transpose() {
    __shared__ fp16 tile[32][33];
    const int d0 = blockIdx.x * 32;
    const int s0 = blockIdx.y * 32;
    const int bh = blockIdx.z;
    const int tx = threadIdx.x, ty = threadIdx.y;
#pragma unroll
    for (int r = 0; r < 4; r++)
        tile[ty + r * 8][tx] =
            g_V16[(size_t)bh * SEQ * DH + (size_t)(s0 + ty + r * 8) * DH + d0 + tx];
    __syncthreads();
#pragma unroll
    for (int r = 0; r < 4; r++)
        g_Vt16[(size_t)bh * DH * SEQ + (size_t)(d0 + ty + r * 8) * SEQ + s0 + tx] =
            tile[tx][ty + r * 8];
}

// ---------------------------------------------------------------------------
// Kernel: causal scores = Q . K^T (fp32 to g_S). Triangular launch.
// ---------------------------------------------------------------------------
__global__ void __launch_bounds__(256, 2)
k_scores() {
    const int t = blockIdx.x;
    int bi = (int)((sqrtf(8.f * (float)t + 1.f) - 1.f) * 0.5f);
    if ((bi + 1) * (bi + 2) / 2 <= t) bi++;
    else if (bi * (bi + 1) / 2 > t) bi--;
    const int bj = t - bi * (bi + 1) / 2;
    const int bh = blockIdx.y;

    extern __shared__ char sm[];
    const uint32_t sb = smem_u32(sm);

    const size_t hb = (size_t)bh * SEQ * DH;
    float acc[2][8][4];
    gemm_mainloop(sb,
        g_Qh + hb + (size_t)bi * 128 * DH, g_Qm + hb + (size_t)bi * 128 * DH, DH,
        g_Kh + hb + (size_t)bj * 128 * DH, g_Km + hb + (size_t)bj * 128 * DH, DH,
        DH / 32, acc);

    const int tid = threadIdx.x, lane = tid & 31, wid = tid >> 5;
    const int wm = wid >> 1, wn = wid & 1;
    float* Sp = g_S + (size_t)bh * SEQ * SEQ;
#pragma unroll
    for (int mb = 0; mb < 2; mb++)
#pragma unroll
        for (int rp = 0; rp < 2; rp++) {
            const int m = bi * 128 + wm * 32 + mb * 16 + (lane >> 2) + rp * 8;
            float* dst = Sp + (size_t)m * SEQ + bj * 128;
#pragma unroll
            for (int j = 0; j < 8; j++) {
                const int col = wn * 64 + j * 8 + (lane & 3) * 2;
                *(float2*)(dst + col) =
                    make_float2(acc[mb][j][rp * 2], acc[mb][j][rp * 2 + 1]);
            }
        }
}

// ---------------------------------------------------------------------------
// Kernel: row softmax (vectorized, causal-skipped loads). In-place single
// fp16 probs into the g_S row; fp32 probs to Pext when use_ext.
// ---------------------------------------------------------------------------
__device__ __forceinline__ float warp_max(float v) {
#pragma unroll
    for (int o = 16; o > 0; o >>= 1) v = fmaxf(v, __shfl_xor_sync(0xffffffffu, v, o));
    return v;
}
__device__ __forceinline__ float warp_sum(float v) {
#pragma unroll
    for (int o = 16; o > 0; o >>= 1) v += __shfl_xor_sync(0xffffffffu, v, o);
    return v;
}

__global__ void __launch_bounds__(256)
k_softmax(float* __restrict__ Pext, int use_ext) {
    __shared__ float shm[8];
    __shared__ float shs[8];

    const size_t row = blockIdx.x;
    const int q = (int)(row & (SEQ - 1));
    const float* pr = g_S + row * (size_t)SEQ;
    const int tid = threadIdx.x;
    const int wid = tid >> 5, lid = tid & 31;
    const int jb = tid * 8;

    float v[8];
    if (jb <= q) {
        float4 a = *(const float4*)(pr + jb);
        float4 b = *(const float4*)(pr + jb + 4);
        v[0] = a.x; v[1] = a.y; v[2] = a.z; v[3] = a.w;
        v[4] = b.x; v[5] = b.y; v[6] = b.z; v[7] = b.w;
#pragma unroll
        for (int k = 0; k < 8; k++)
            if (jb + k > q) v[k] = -CUDART_INF_F;
    } else {
#pragma unroll
        for (int k = 0; k < 8; k++) v[k] = -CUDART_INF_F;
    }
    float m = -CUDART_INF_F;
#pragma unroll
    for (int k = 0; k < 8; k++) m = fmaxf(m, v[k]);
    m = warp_max(m);
    if (lid == 0) shm[wid] = m;
    __syncthreads();          // all row reads precede in-place writes
    if (tid < 32) {
        float t = (tid < 8) ? shm[tid] : -CUDART_INF_F;
        t = warp_max(t);
        if (tid == 0) shm[0] = t;
    }
    __syncthreads();
    m = shm[0];

    float s = 0.f;
#pragma unroll
    for (int k = 0; k < 8; k++) {
        const float e = expf(v[k] - m);
        v[k] = e;
        s += e;
    }
    s = warp_sum(s);
    if (lid == 0) shs[wid] = s;
    __syncthreads();
    if (tid < 32) {
        float t = (tid < 8) ? shs[tid] : 0.f;
        t = warp_sum(t);
        if (tid == 0) shs[0] = t;
    }
    __syncthreads();
    const float inv = 1.f / shs[0];

#pragma unroll
    for (int k = 0; k < 8; k++) v[k] *= inv;

    if (use_ext) {
        float* po = Pext + row * (size_t)SEQ + jb;
        *(float4*)(po)     = make_float4(v[0], v[1], v[2], v[3]);
        *(float4*)(po + 4) = make_float4(v[4], v[5], v[6], v[7]);
    }

    const int jmax = ((q >> 7) + 1) << 7;      // 128-aligned
    if (jb < jmax) {
        fp16* ph = (fp16*)(g_S) + row * (size_t)(2 * SEQ) + jb;  // row = 8KB
        alignas(16) fp16 h[8];
#pragma unroll
        for (int k = 0; k < 8; k++) h[k] = __float2half(v[k]);
        *(uint4*)ph = *(const uint4*)h;
    }
}

// ---------------------------------------------------------------------------
// Kernel: AV = P . V (fp16 single x single, causal-truncated).
// grid (bh=64, ybi=16), longest-first. Epilogue: single fp16 into g_AO16.
// ---------------------------------------------------------------------------
__global__ void __launch_bounds__(256, 2)
k_av() {
    const int bh = blockIdx.x;
    const int bi = 15 - (int)blockIdx.y;
    extern __shared__ char sm[];
    const uint32_t sb = smem_u32(sm);

    const fp16* Pbase = (const fp16*)(g_S) +
                        (size_t)(bh * SEQ + bi * 128) * (size_t)(2 * SEQ);

    float acc[2][8][4];
    gemm_mainloop_11(sb,
        Pbase, 2 * SEQ,
        g_Vt16 + (size_t)bh * DH * SEQ, SEQ,
        (bi + 1) * 4, acc);

    const int tid = threadIdx.x, lane = tid & 31, wid = tid >> 5;
    const int wm = wid >> 1, wn = wid & 1;
    const int b = bh >> 4, h = bh & 15;
#pragma unroll
    for (int mb = 0; mb < 2; mb++)
#pragma unroll
        for (int rp = 0; rp < 2; rp++) {
            const int s = bi * 128 + wm * 32 + mb * 16 + (lane >> 2) + rp * 8;
            fp16* po = g_AO16 + ((size_t)(b * SEQ + s)) * DM + h * 128;
#pragma unroll
            for (int j = 0; j < 8; j++) {
                const int col = wn * 64 + j * 8 + (lane & 3) * 2;
                __half2 hv = __floats2half2_rn(acc[mb][j][rp * 2 + 0],
                                               acc[mb][j][rp * 2 + 1]);
                *(__half2*)(po + col) = hv;
            }
        }
}

// ---------------------------------------------------------------------------
// Kernel: out = AO . Wo^T + bo (fp16 single x single, fp32 to d_out).
// ---------------------------------------------------------------------------
__global__ void __launch_bounds__(256, 2)
k_out(const float* __restrict__ bias, float* __restrict__ Out) {
    extern __shared__ char sm[];
    const uint32_t sb = smem_u32(sm);
    const int nt = blockIdx.x, mt = blockIdx.y;

    float acc[2][8][4];
    gemm_mainloop_11(sb,
        g_AO16 + (size_t)mt * 128 * DM, DM,
        g_Wo16 + (size_t)nt * 128 * DM, DM,
        DM / 32, acc);

    const int tid = threadIdx.x, lane = tid & 31, wid = tid >> 5;
    const int wm = wid >> 1, wn = wid & 1;
#pragma unroll
    for (int mb = 0; mb < 2; mb++)
#pragma unroll
        for (int rp = 0; rp < 2; rp++) {
            const int m = mt * 128 + wm * 32 + mb * 16 + (lane >> 2) + rp * 8;
            float* dst = Out + (size_t)m * DM + nt * 128;
#pragma unroll
            for (int j = 0; j < 8; j++) {
                const int col = wn * 64 + j * 8 + (lane & 3) * 2;
                *(float2*)(dst + col) =
                    make_float2(acc[mb][j][rp * 2] + bias[nt * 128 + col],
                                acc[mb][j][rp * 2 + 1] + bias[nt * 128 + col + 1]);
            }
        }
}

// ---------------------------------------------------------------------------
// Launch
// ---------------------------------------------------------------------------
extern "C" void kernel_launch(void* const* d_in, const int* in_sizes, int n_in,
                              void* d_out, int out_size) {
    const float* hs = (const float*)d_in[0];
    const float* wq = (const float*)d_in[1];
    const float* wk = (const float*)d_in[2];
    const float* wv = (const float*)d_in[3];
    const float* wo = (const float*)d_in[4];
    const float* bo = (const float*)d_in[5];
    float* out = (float*)d_out;

    const long long OUT_ELEMS = (long long)MROWS * DM;       // 16,777,216
    const long long WEI_ELEMS = (long long)BH * SEQ * SEQ;   // 268,435,456
    const int use_ext = ((long long)out_size >= OUT_ELEMS + WEI_ELEMS) ? 1 : 0;
    float* Pext = use_ext ? (out + OUT_ELEMS) : nullptr;

    cudaFuncSetAttribute(k_proj,   cudaFuncAttributeMaxDynamicSharedMemorySize, SMEM_GEMM);
    cudaFuncSetAttribute(k_scores, cudaFuncAttributeMaxDynamicSharedMemorySize, SMEM_GEMM);
    cudaFuncSetAttribute(k_av,     cudaFuncAttributeMaxDynamicSharedMemorySize, SMEM_GEMM11);
    cudaFuncSetAttribute(k_out,    cudaFuncAttributeMaxDynamicSharedMemorySize, SMEM_GEMM11);

    const long NH4 = (long)MROWS * DM / 4;   // 4,194,304
    const long NW4 = (long)DM * DM / 4;      // 1,048,576
    const long totq = NH4 + 4 * NW4;         // 8,388,608
    k_convert_all<<<(unsigned)((totq + 255) / 256), 256>>>(hs, wq, wk, wv, wo);

    k_proj<<<dim3(16, 64, 3), 256, SMEM_GEMM>>>();

    k_transpose<<<dim3(4, 64, BH), dim3(32, 8)>>>();

    k_scores<<<dim3(136, BH), 256, SMEM_GEMM>>>();
    k_softmax<<<BH * SEQ, 256>>>(Pext, use_ext);
    k_av<<<dim3(BH, 16), 256, SMEM_GEMM11>>>();
    k_out<<<dim3(16, 64), 256, SMEM_GEMM11>>>(bo, out);
}